// round 1
// baseline (speedup 1.0000x reference)
#include <cuda_runtime.h>
#include <math.h>

#define RES      2048
#define STEPS    65536
#define W        32
#define CHUNK    256
#define TILE     64
#define NTHREADS 256
#define BATCH    16
#define INV2SIG2 5000.0f   // 1/(2*0.01^2)

__global__ __launch_bounds__(NTHREADS)
void bezier_raster_kernel(const float* __restrict__ cp, float* __restrict__ out)
{
    __shared__ float sCx[CHUNK], sCy[CHUNK];
    __shared__ int   sBx[CHUNK], sBy[CHUNK];
    __shared__ int   sMinX, sMaxX, sMinY, sMaxY;
    __shared__ float ebufx[BATCH][TILE];
    __shared__ float ebufy[BATCH][TILE];

    const int tid = threadIdx.x;
    const int s0  = blockIdx.x * CHUNK;

    const double p0x = (double)cp[0], p0y = (double)cp[1];
    const double p1x = (double)cp[2], p1y = (double)cp[3];
    const double p2x = (double)cp[4], p2y = (double)cp[5];

    if (tid == 0) {
        sMinX = 0x7fffffff; sMaxX = -0x7fffffff;
        sMinY = 0x7fffffff; sMaxY = -0x7fffffff;
    }

    // ---- Phase A: per-step curve point + block corner (fp64 for floor robustness)
    int   myBx, myBy;
    {
        const int s = s0 + tid;
        const double tl = (double)s / 65535.0;   // linspace(0,1,STEPS)
        const double to = (double)s / 65536.0;   // arange(STEPS)/STEPS
        const double ax = p0x + (p1x - p0x) * tl;
        const double bx = p1x + (p2x - p1x) * tl;
        const double ay = p0y + (p1y - p0y) * tl;
        const double by = p1y + (p2y - p1y) * tl;
        const double cx = ax + to * (bx - ax);
        const double cy = ay + to * (by - ay);
        int bxi = (int)floor((double)RES * cx) - W / 2;
        int byi = (int)floor((double)RES * cy) - W / 2;
        bxi = min(max(bxi, 0), RES - W);
        byi = min(max(byi, 0), RES - W);
        myBx = bxi; myBy = byi;
        sCx[tid] = (float)cx; sCy[tid] = (float)cy;
        sBx[tid] = bxi;       sBy[tid] = byi;
    }
    __syncthreads();
    atomicMin(&sMinX, myBx); atomicMax(&sMaxX, myBx);
    atomicMin(&sMinY, myBy); atomicMax(&sMaxY, myBy);
    __syncthreads();

    const int basex = sMinX, basey = sMinY;
    const bool ok = (sMaxX + W - basex <= TILE) && (sMaxY + W - basey <= TILE);
    const float scale = 1.0f / (float)STEPS;

    if (ok) {
        // ---- Tiled path: thread (ty,tx) owns rows [ty*4, ty*4+4) x cols [tx*4, tx*4+4)
        const int ty = tid >> 4;
        const int tx = tid & 15;
        float acc[4][4];
        #pragma unroll
        for (int r = 0; r < 4; ++r)
            #pragma unroll
            for (int c = 0; c < 4; ++c) acc[r][c] = 0.0f;

        for (int b = 0; b < CHUNK / BATCH; ++b) {
            // compute separable weights for BATCH steps: 2048 values / 256 threads
            #pragma unroll
            for (int k = 0; k < (BATCH * 2 * TILE) / NTHREADS; ++k) {
                const int idx  = tid + k * NTHREADS;
                const int sloc = idx >> 7;          // step within batch
                const int rem  = idx & 127;
                const int axis = rem >> 6;          // 0 = x, 1 = y
                const int i    = rem & 63;          // tile index
                const int sg   = b * BATCH + sloc;  // step within chunk
                float w = 0.0f;
                if (axis == 0) {
                    const int gx  = basex + i;
                    const int blk = sBx[sg];
                    if (gx >= blk && gx < blk + W) {
                        const float d = sCx[sg] - (float)gx * (1.0f / RES);
                        w = __expf(-INV2SIG2 * d * d);
                    }
                    ebufx[sloc][i] = w;
                } else {
                    const int gy  = basey + i;
                    const int blk = sBy[sg];
                    if (gy >= blk && gy < blk + W) {
                        const float d = sCy[sg] - (float)gy * (1.0f / RES);
                        w = __expf(-INV2SIG2 * d * d);
                    }
                    ebufy[sloc][i] = w;
                }
            }
            __syncthreads();

            #pragma unroll 4
            for (int sl = 0; sl < BATCH; ++sl) {
                const float4 ex = *(const float4*)&ebufx[sl][ty * 4];
                const float4 ey = *(const float4*)&ebufy[sl][tx * 4];
                acc[0][0] += ex.x * ey.x;  acc[0][1] += ex.x * ey.y;
                acc[0][2] += ex.x * ey.z;  acc[0][3] += ex.x * ey.w;
                acc[1][0] += ex.y * ey.x;  acc[1][1] += ex.y * ey.y;
                acc[1][2] += ex.y * ey.z;  acc[1][3] += ex.y * ey.w;
                acc[2][0] += ex.z * ey.x;  acc[2][1] += ex.z * ey.y;
                acc[2][2] += ex.z * ey.z;  acc[2][3] += ex.z * ey.w;
                acc[3][0] += ex.w * ey.x;  acc[3][1] += ex.w * ey.y;
                acc[3][2] += ex.w * ey.z;  acc[3][3] += ex.w * ey.w;
            }
            __syncthreads();
        }

        // ---- Epilogue: spread-address atomics (tiles of adjacent CTAs overlap)
        #pragma unroll
        for (int r = 0; r < 4; ++r) {
            #pragma unroll
            for (int c = 0; c < 4; ++c) {
                const float v = acc[r][c];
                if (v != 0.0f) {
                    const int gx = basex + ty * 4 + r;
                    const int gy = basey + tx * 4 + c;
                    if (gx < RES && gy < RES)
                        atomicAdd(&out[gx * RES + gy], v * scale);
                }
            }
        }
    } else {
        // ---- Fallback (bbox exceeded tile; should never trigger for points in [0,1])
        for (int sl = 0; sl < CHUNK; ++sl) {
            const int   blkx = sBx[sl], blky = sBy[sl];
            const float cx = sCx[sl], cy = sCy[sl];
            for (int c = tid; c < W * W; c += NTHREADS) {
                const int wi = c >> 5, wj = c & 31;
                const int gx = blkx + wi, gy = blky + wj;
                const float dx = cx - (float)gx * (1.0f / RES);
                const float dy = cy - (float)gy * (1.0f / RES);
                const float w = __expf(-INV2SIG2 * (dx * dx + dy * dy));
                atomicAdd(&out[gx * RES + gy], w * scale);
            }
        }
    }
}

extern "C" void kernel_launch(void* const* d_in, const int* in_sizes, int n_in,
                              void* d_out, int out_size)
{
    (void)in_sizes; (void)n_in;
    const float* cp = (const float*)d_in[0];
    float* out = (float*)d_out;
    cudaMemsetAsync(out, 0, (size_t)out_size * sizeof(float), 0);
    bezier_raster_kernel<<<STEPS / CHUNK, NTHREADS>>>(cp, out);
}

// round 2
// speedup vs baseline: 1.3125x; 1.3125x over previous
#include <cuda_runtime.h>
#include <math.h>

#define RES      2048
#define STEPS    65536
#define W        32
#define CHUNK    128
#define TILE     64
#define NTHREADS 256
#define BATCH    16
#define NB       (CHUNK / BATCH)
#define INV2SIG2 5000.0f   // 1/(2*0.01^2)

__global__ __launch_bounds__(NTHREADS, 4)
void bezier_raster_kernel(const float* __restrict__ cp, float* __restrict__ out)
{
    __shared__ float sCx[CHUNK], sCy[CHUNK];
    __shared__ int   sBx[CHUNK], sBy[CHUNK];
    __shared__ int   sMinX, sMaxX, sMinY, sMaxY;
    __shared__ int   sBminX[NB], sBmaxX[NB];
    __shared__ float ebufx[BATCH][TILE];
    __shared__ float ebufy[BATCH][TILE];

    const int tid = threadIdx.x;
    const int s0  = blockIdx.x * CHUNK;

    const double p0x = (double)cp[0], p0y = (double)cp[1];
    const double p1x = (double)cp[2], p1y = (double)cp[3];
    const double p2x = (double)cp[4], p2y = (double)cp[5];

    if (tid == 0) {
        sMinX = 0x7fffffff; sMaxX = -0x7fffffff;
        sMinY = 0x7fffffff; sMaxY = -0x7fffffff;
    }

    // ---- Phase A: per-step curve point + block corner (fp64 for floor robustness)
    int myBx, myBy;
    {
        const int s = s0 + ((tid < CHUNK) ? tid : (CHUNK - 1));
        const double tl = (double)s / 65535.0;   // linspace(0,1,STEPS)
        const double to = (double)s / 65536.0;   // arange(STEPS)/STEPS
        const double ax = p0x + (p1x - p0x) * tl;
        const double bx = p1x + (p2x - p1x) * tl;
        const double ay = p0y + (p1y - p0y) * tl;
        const double by = p1y + (p2y - p1y) * tl;
        const double cx = ax + to * (bx - ax);
        const double cy = ay + to * (by - ay);
        int bxi = (int)floor((double)RES * cx) - W / 2;
        int byi = (int)floor((double)RES * cy) - W / 2;
        bxi = min(max(bxi, 0), RES - W);
        byi = min(max(byi, 0), RES - W);
        myBx = bxi; myBy = byi;
        if (tid < CHUNK) {
            sCx[tid] = (float)cx; sCy[tid] = (float)cy;
            sBx[tid] = bxi;       sBy[tid] = byi;
        }
    }
    __syncthreads();
    atomicMin(&sMinX, myBx); atomicMax(&sMaxX, myBx);
    atomicMin(&sMinY, myBy); atomicMax(&sMaxY, myBy);
    __syncthreads();

    // per-batch x-band (rows) for warp-level skip
    if (tid < NB) {
        int mn = 0x7fffffff, mx = -0x7fffffff;
        #pragma unroll
        for (int k = 0; k < BATCH; ++k) {
            const int v = sBx[tid * BATCH + k];
            mn = min(mn, v); mx = max(mx, v);
        }
        sBminX[tid] = mn; sBmaxX[tid] = mx;
    }
    __syncthreads();

    const int basex = sMinX, basey = sMinY;
    const bool ok = (sMaxX + W - basex <= TILE) && (sMaxY + W - basey <= TILE);
    const float scale = 1.0f / (float)STEPS;

    if (ok) {
        // ---- Tiled path: thread (ty,tx) owns rows [ty*4, ty*4+4) x cols [tx*4, tx*4+4)
        const int ty   = tid >> 4;
        const int tx   = tid & 15;
        const int wrow = (tid >> 5) * 8;   // warp owns tile rows [wrow, wrow+8)
        float acc[4][4];
        #pragma unroll
        for (int r = 0; r < 4; ++r)
            #pragma unroll
            for (int c = 0; c < 4; ++c) acc[r][c] = 0.0f;

        for (int b = 0; b < NB; ++b) {
            // compute separable weights for BATCH steps: 2048 values / 256 threads
            #pragma unroll
            for (int k = 0; k < (BATCH * 2 * TILE) / NTHREADS; ++k) {
                const int idx  = tid + k * NTHREADS;
                const int sloc = idx >> 7;          // step within batch
                const int rem  = idx & 127;
                const int axis = rem >> 6;          // 0 = x, 1 = y
                const int i    = rem & 63;          // tile index
                const int sg   = b * BATCH + sloc;  // step within chunk
                float w = 0.0f;
                if (axis == 0) {
                    const int gx  = basex + i;
                    const int blk = sBx[sg];
                    if (gx >= blk && gx < blk + W) {
                        const float d = sCx[sg] - (float)gx * (1.0f / RES);
                        w = __expf(-INV2SIG2 * d * d);
                    }
                    ebufx[sloc][i] = w;
                } else {
                    const int gy  = basey + i;
                    const int blk = sBy[sg];
                    if (gy >= blk && gy < blk + W) {
                        const float d = sCy[sg] - (float)gy * (1.0f / RES);
                        w = __expf(-INV2SIG2 * d * d);
                    }
                    ebufy[sloc][i] = w;
                }
            }
            __syncthreads();

            // warp-level exact skip: if this warp's 8 rows are outside the
            // batch's x-band, every ex it would load is zero.
            const int lo = sBminX[b] - basex;        // first covered row
            const int hi = sBmaxX[b] - basex + W;    // one past last covered row
            if (wrow + 8 > lo && wrow < hi) {
                #pragma unroll 4
                for (int sl = 0; sl < BATCH; ++sl) {
                    const float4 ex = *(const float4*)&ebufx[sl][ty * 4];
                    const float4 ey = *(const float4*)&ebufy[sl][tx * 4];
                    acc[0][0] += ex.x * ey.x;  acc[0][1] += ex.x * ey.y;
                    acc[0][2] += ex.x * ey.z;  acc[0][3] += ex.x * ey.w;
                    acc[1][0] += ex.y * ey.x;  acc[1][1] += ex.y * ey.y;
                    acc[1][2] += ex.y * ey.z;  acc[1][3] += ex.y * ey.w;
                    acc[2][0] += ex.z * ey.x;  acc[2][1] += ex.z * ey.y;
                    acc[2][2] += ex.z * ey.z;  acc[2][3] += ex.z * ey.w;
                    acc[3][0] += ex.w * ey.x;  acc[3][1] += ex.w * ey.y;
                    acc[3][2] += ex.w * ey.z;  acc[3][3] += ex.w * ey.w;
                }
            }
            __syncthreads();
        }

        // ---- Epilogue: spread-address atomics (tiles of adjacent CTAs overlap)
        #pragma unroll
        for (int r = 0; r < 4; ++r) {
            #pragma unroll
            for (int c = 0; c < 4; ++c) {
                const float v = acc[r][c];
                if (v != 0.0f) {
                    const int gx = basex + ty * 4 + r;
                    const int gy = basey + tx * 4 + c;
                    if (gx < RES && gy < RES)
                        atomicAdd(&out[gx * RES + gy], v * scale);
                }
            }
        }
    } else {
        // ---- Fallback (bbox exceeded tile; should never trigger for points in [0,1])
        for (int sl = 0; sl < CHUNK; ++sl) {
            const int   blkx = sBx[sl], blky = sBy[sl];
            const float cx = sCx[sl], cy = sCy[sl];
            for (int c = tid; c < W * W; c += NTHREADS) {
                const int wi = c >> 5, wj = c & 31;
                const int gx = blkx + wi, gy = blky + wj;
                const float dx = cx - (float)gx * (1.0f / RES);
                const float dy = cy - (float)gy * (1.0f / RES);
                const float w = __expf(-INV2SIG2 * (dx * dx + dy * dy));
                atomicAdd(&out[gx * RES + gy], w * scale);
            }
        }
    }
}

extern "C" void kernel_launch(void* const* d_in, const int* in_sizes, int n_in,
                              void* d_out, int out_size)
{
    (void)in_sizes; (void)n_in;
    const float* cp = (const float*)d_in[0];
    float* out = (float*)d_out;
    cudaMemsetAsync(out, 0, (size_t)out_size * sizeof(float), 0);
    bezier_raster_kernel<<<STEPS / CHUNK, NTHREADS>>>(cp, out);
}

// round 3
// speedup vs baseline: 1.7364x; 1.3230x over previous
#include <cuda_runtime.h>
#include <math.h>

#define RES      2048
#define STEPS    65536
#define W        32
#define CHUNK    128
#define TILE     64
#define EPAD     72
#define NTHREADS 256
#define BATCH    16
#define NB       (CHUNK / BATCH)
#define INV2SIG2 5000.0f   // 1/(2*0.01^2)

__device__ __forceinline__ unsigned to_tf32(float f) {
    unsigned r; asm("cvt.rna.tf32.f32 %0, %1;" : "=r"(r) : "f"(f)); return r;
}

__global__ __launch_bounds__(NTHREADS, 4)
void bezier_raster_kernel(const float* __restrict__ cp, float* __restrict__ out)
{
    __shared__ float sCx[CHUNK], sCy[CHUNK];
    __shared__ int   sBx[CHUNK], sBy[CHUNK];
    __shared__ int   sMinX, sMaxX, sMinY, sMaxY;
    __shared__ int   sBminX[NB], sBmaxX[NB], sBminY[NB], sBmaxY[NB];
    __shared__ unsigned ebufx[BATCH][EPAD];   // tf32 bits, [sl][row]
    __shared__ unsigned ebufy[BATCH][EPAD];   // tf32 bits, [sl][col]

    const int tid = threadIdx.x;
    const int s0  = blockIdx.x * CHUNK;

    const double p0x = (double)cp[0], p0y = (double)cp[1];
    const double p1x = (double)cp[2], p1y = (double)cp[3];
    const double p2x = (double)cp[4], p2y = (double)cp[5];

    if (tid == 0) {
        sMinX = 0x7fffffff; sMaxX = -0x7fffffff;
        sMinY = 0x7fffffff; sMaxY = -0x7fffffff;
    }

    // ---- Phase A: per-step curve point + block corner (fp64 for floor robustness)
    int myBx, myBy;
    {
        const int s = s0 + ((tid < CHUNK) ? tid : (CHUNK - 1));
        const double tl = (double)s * (1.0 / 65535.0);   // linspace(0,1,STEPS)
        const double to = (double)s * (1.0 / 65536.0);   // arange(STEPS)/STEPS
        const double ax = p0x + (p1x - p0x) * tl;
        const double bx = p1x + (p2x - p1x) * tl;
        const double ay = p0y + (p1y - p0y) * tl;
        const double by = p1y + (p2y - p1y) * tl;
        const double cx = ax + to * (bx - ax);
        const double cy = ay + to * (by - ay);
        int bxi = (int)floor((double)RES * cx) - W / 2;
        int byi = (int)floor((double)RES * cy) - W / 2;
        bxi = min(max(bxi, 0), RES - W);
        byi = min(max(byi, 0), RES - W);
        myBx = bxi; myBy = byi;
        if (tid < CHUNK) {
            sCx[tid] = (float)cx; sCy[tid] = (float)cy;
            sBx[tid] = bxi;       sBy[tid] = byi;
        }
    }
    __syncthreads();
    atomicMin(&sMinX, myBx); atomicMax(&sMaxX, myBx);
    atomicMin(&sMinY, myBy); atomicMax(&sMaxY, myBy);
    __syncthreads();

    // per-batch x/y bands for warp-level skip
    if (tid < 2 * NB) {
        const int b   = tid & (NB - 1);
        const int axs = tid >> 3;              // 0 = x, 1 = y (NB == 8)
        const int* src = axs ? sBy : sBx;
        int mn = 0x7fffffff, mx = -0x7fffffff;
        #pragma unroll
        for (int k = 0; k < BATCH; ++k) {
            const int v = src[b * BATCH + k];
            mn = min(mn, v); mx = max(mx, v);
        }
        if (axs) { sBminY[b] = mn; sBmaxY[b] = mx; }
        else     { sBminX[b] = mn; sBmaxX[b] = mx; }
    }
    __syncthreads();

    const int basex = sMinX, basey = sMinY;
    const bool ok = (sMaxX + W - basex <= TILE) && (sMaxY + W - basey <= TILE);
    const float scale = 1.0f / (float)STEPS;

    if (ok) {
        // warp w owns C rows [rb, rb+16) x cols [cb, cb+32) of the 64x64 tile
        const int lane = tid & 31;
        const int wid  = tid >> 5;
        const int g    = lane >> 2;     // groupID
        const int t    = lane & 3;      // threadID_in_group
        const int rb   = (wid >> 1) * 16;
        const int cb   = (wid & 1)  * 32;

        float c[4][4];
        #pragma unroll
        for (int n = 0; n < 4; ++n)
            #pragma unroll
            for (int i = 0; i < 4; ++i) c[n][i] = 0.0f;

        for (int b = 0; b < NB; ++b) {
            // separable tf32 weights for BATCH steps: 2048 values / 256 threads
            #pragma unroll
            for (int k = 0; k < (BATCH * 2 * TILE) / NTHREADS; ++k) {
                const int idx  = tid + k * NTHREADS;
                const int sloc = idx >> 7;
                const int rem  = idx & 127;
                const int axis = rem >> 6;
                const int i    = rem & 63;
                const int sg   = b * BATCH + sloc;
                float w = 0.0f;
                if (axis == 0) {
                    const int gx  = basex + i;
                    const int blk = sBx[sg];
                    if (gx >= blk && gx < blk + W) {
                        const float d = sCx[sg] - (float)gx * (1.0f / RES);
                        w = __expf(-INV2SIG2 * d * d);
                    }
                    ebufx[sloc][i] = to_tf32(w);
                } else {
                    const int gy  = basey + i;
                    const int blk = sBy[sg];
                    if (gy >= blk && gy < blk + W) {
                        const float d = sCy[sg] - (float)gy * (1.0f / RES);
                        w = __expf(-INV2SIG2 * d * d);
                    }
                    ebufy[sloc][i] = to_tf32(w);
                }
            }
            __syncthreads();

            // exact warp skip: batch footprint is [xband] x [yband]
            const int rlo = sBminX[b] - basex, rhi = sBmaxX[b] - basex + W;
            const int clo = sBminY[b] - basey, chi = sBmaxY[b] - basey + W;
            if ((rb + 16 > rlo) && (rb < rhi) && (cb + 32 > clo) && (cb < chi)) {
                #pragma unroll
                for (int ks = 0; ks < 2; ++ks) {
                    const int k0 = ks * 8;
                    const unsigned a0 = ebufx[k0 + t][rb + g];
                    const unsigned a1 = ebufx[k0 + t][rb + g + 8];
                    const unsigned a2 = ebufx[k0 + t + 4][rb + g];
                    const unsigned a3 = ebufx[k0 + t + 4][rb + g + 8];
                    #pragma unroll
                    for (int n = 0; n < 4; ++n) {
                        const unsigned b0 = ebufy[k0 + t][cb + n * 8 + g];
                        const unsigned b1 = ebufy[k0 + t + 4][cb + n * 8 + g];
                        asm volatile(
                            "mma.sync.aligned.m16n8k8.row.col.f32.tf32.tf32.f32 "
                            "{%0,%1,%2,%3},{%4,%5,%6,%7},{%8,%9},{%0,%1,%2,%3};"
                            : "+f"(c[n][0]), "+f"(c[n][1]), "+f"(c[n][2]), "+f"(c[n][3])
                            : "r"(a0), "r"(a1), "r"(a2), "r"(a3), "r"(b0), "r"(b1));
                    }
                }
            }
            __syncthreads();
        }

        // ---- Epilogue: spread-address atomics
        const int row0 = basex + rb + g;
        const int row1 = row0 + 8;
        #pragma unroll
        for (int n = 0; n < 4; ++n) {
            const int col = basey + cb + n * 8 + 2 * t;
            if (c[n][0] != 0.0f && row0 < RES && col     < RES) atomicAdd(&out[row0 * RES + col],     c[n][0] * scale);
            if (c[n][1] != 0.0f && row0 < RES && col + 1 < RES) atomicAdd(&out[row0 * RES + col + 1], c[n][1] * scale);
            if (c[n][2] != 0.0f && row1 < RES && col     < RES) atomicAdd(&out[row1 * RES + col],     c[n][2] * scale);
            if (c[n][3] != 0.0f && row1 < RES && col + 1 < RES) atomicAdd(&out[row1 * RES + col + 1], c[n][3] * scale);
        }
    } else {
        // ---- Fallback (bbox exceeded tile; should never trigger for points in [0,1])
        for (int sl = 0; sl < CHUNK; ++sl) {
            const int   blkx = sBx[sl], blky = sBy[sl];
            const float cx = sCx[sl], cy = sCy[sl];
            for (int c2 = tid; c2 < W * W; c2 += NTHREADS) {
                const int wi = c2 >> 5, wj = c2 & 31;
                const int gx = blkx + wi, gy = blky + wj;
                const float dx = cx - (float)gx * (1.0f / RES);
                const float dy = cy - (float)gy * (1.0f / RES);
                const float w = __expf(-INV2SIG2 * (dx * dx + dy * dy));
                atomicAdd(&out[gx * RES + gy], w * scale);
            }
        }
    }
}

extern "C" void kernel_launch(void* const* d_in, const int* in_sizes, int n_in,
                              void* d_out, int out_size)
{
    (void)in_sizes; (void)n_in;
    const float* cp = (const float*)d_in[0];
    float* out = (float*)d_out;
    cudaMemsetAsync(out, 0, (size_t)out_size * sizeof(float), 0);
    bezier_raster_kernel<<<STEPS / CHUNK, NTHREADS>>>(cp, out);
}

// round 4
// speedup vs baseline: 2.2513x; 1.2965x over previous
#include <cuda_runtime.h>
#include <math.h>

#define RES      2048
#define STEPS    65536
#define W        32
#define CHUNK    128
#define TILE     64
#define EPAD     72
#define NTHREADS 256
#define BATCH    16
#define NB       (CHUNK / BATCH)
#define AA       5000.0f            // 1/(2 sigma^2)
#define DLT      (1.0f/2048.0f)
#define AD2      0.0011920929f      // AA * DLT^2
#define INV2SIG2 5000.0f

__device__ __forceinline__ unsigned to_tf32(float f) {
    unsigned r; asm("cvt.rna.tf32.f32 %0, %1;" : "=r"(r) : "f"(f)); return r;
}

__global__ __launch_bounds__(NTHREADS, 4)
void bezier_raster_kernel(const float* __restrict__ cp, float* __restrict__ out)
{
    __shared__ float sCx[CHUNK], sCy[CHUNK];
    __shared__ int   sBx[CHUNK], sBy[CHUNK];
    __shared__ float sW[2][CHUNK], sE[2][CHUNK];     // per (axis, step) seeds
    __shared__ int   sMinX, sMaxX, sMinY, sMaxY;
    __shared__ int   sBminX[NB], sBmaxX[NB], sBminY[NB], sBmaxY[NB];
    __shared__ unsigned ebx[2][BATCH][EPAD];         // tf32 bits, double-buffered
    __shared__ unsigned eby[2][BATCH][EPAD];

    const int tid = threadIdx.x;
    const int s0  = blockIdx.x * CHUNK;

    if (tid == 0) {
        sMinX = 0x7fffffff; sMaxX = -0x7fffffff;
        sMinY = 0x7fffffff; sMaxY = -0x7fffffff;
    }
    __syncthreads();

    // ---- Phase A: per-step curve point + block corner (fp64, 128 threads only)
    if (tid < CHUNK) {
        const int s = s0 + tid;
        const double tl = (double)s * (1.0 / 65535.0);   // linspace(0,1,STEPS)
        const double to = (double)s * (1.0 / 65536.0);   // arange(STEPS)/STEPS
        const double p0x = (double)cp[0], p0y = (double)cp[1];
        const double p1x = (double)cp[2], p1y = (double)cp[3];
        const double p2x = (double)cp[4], p2y = (double)cp[5];
        const double ax = p0x + (p1x - p0x) * tl;
        const double bx = p1x + (p2x - p1x) * tl;
        const double ay = p0y + (p1y - p0y) * tl;
        const double by = p1y + (p2y - p1y) * tl;
        const double cx = ax + to * (bx - ax);
        const double cy = ay + to * (by - ay);
        int bxi = (int)floor((double)RES * cx) - W / 2;
        int byi = (int)floor((double)RES * cy) - W / 2;
        bxi = min(max(bxi, 0), RES - W);
        byi = min(max(byi, 0), RES - W);
        sCx[tid] = (float)cx; sCy[tid] = (float)cy;
        sBx[tid] = bxi;       sBy[tid] = byi;
        atomicMin(&sMinX, bxi); atomicMax(&sMaxX, bxi);
        atomicMin(&sMinY, byi); atomicMax(&sMaxY, byi);
    }
    __syncthreads();

    const int basex = sMinX, basey = sMinY;

    // ---- Seeds: one thread per (step, axis): 2 expf each, done ONCE per CTA
    {
        const int st = tid >> 1;
        const int ax = tid & 1;
        const float c  = ax ? sCy[st] : sCx[st];
        const int   pb = ax ? basey   : basex;
        const float d00 = c - (float)pb * DLT;
        sW[ax][st] = __expf(-AA * d00 * d00);
        sE[ax][st] = __expf(2.0f * AA * DLT * d00);   // 4.8828125 * d00
    }
    // per-batch x/y bands for warp-level skip (concurrent with seeds)
    if (tid < 2 * NB) {
        const int b   = tid & (NB - 1);
        const int axs = tid >> 3;
        const int* src = axs ? sBy : sBx;
        int mn = 0x7fffffff, mx = -0x7fffffff;
        #pragma unroll
        for (int k = 0; k < BATCH; ++k) {
            const int v = src[b * BATCH + k];
            mn = min(mn, v); mx = max(mx, v);
        }
        if (axs) { sBminY[b] = mn; sBmaxY[b] = mx; }
        else     { sBminX[b] = mn; sBmaxX[b] = mx; }
    }
    __syncthreads();

    const bool ok = (sMaxX + W - basex <= TILE) && (sMaxY + W - basey <= TILE);
    const float scale = 1.0f / (float)STEPS;

    if (ok) {
        // weight-gen decomposition: 16 steps x 2 axes x 8 sub-ranges = 256 units
        const int gsloc = tid >> 4;          // step within batch
        const int gaxis = (tid >> 3) & 1;    // 0 = x, 1 = y
        const int gsub  = tid & 7;           // 8-position group
        // per-thread hoisted constants (4 expf total, once per kernel)
        const float CW  = __expf(-64.0f * AD2 * (float)(gsub * gsub)); // G^{64 s^2}
        const float Crs = __expf(-16.0f * AD2 * (float)gsub);          // g^{8 s}
        const float Gc  = __expf(-AD2);
        const float gc  = __expf(-2.0f * AD2);
        const int   gpb  = gaxis ? basey : basex;
        const int*  gblk = gaxis ? sBy : sBx;

        auto gen = [&](int b, int buf) {
            const int st  = b * BATCH + gsloc;
            const int blk = gblk[st];
            const float w00 = sW[gaxis][st];
            const float E   = sE[gaxis][st];
            const float E2 = E * E, E4 = E2 * E2, E8 = E4 * E4;
            float Ep = (gsub & 1) ? E8 : 1.0f;
            const float E16 = E8 * E8;   if (gsub & 2) Ep *= E16;
            const float E32 = E16 * E16; if (gsub & 4) Ep *= E32;
            float w = w00 * Ep * CW;         // weight at m = 8*sub
            float r = E * Gc * Crs;          // ratio  at m = 8*sub
            const int rel = gpb + gsub * 8 - blk;   // window coord of j=0
            unsigned v[8];
            #pragma unroll
            for (int j = 0; j < 8; ++j) {
                const float wj = ((unsigned)(rel + j) < W) ? w : 0.0f;
                v[j] = to_tf32(wj);
                w *= r; r *= gc;
            }
            unsigned (*dst)[EPAD] = gaxis ? eby[buf] : ebx[buf];
            *(uint4*)&dst[gsloc][gsub * 8]     = make_uint4(v[0], v[1], v[2], v[3]);
            *(uint4*)&dst[gsloc][gsub * 8 + 4] = make_uint4(v[4], v[5], v[6], v[7]);
        };

        // mma decomposition: warp owns C rows [rb,rb+16) x cols [cb,cb+32)
        const int lane = tid & 31;
        const int wid  = tid >> 5;
        const int g    = lane >> 2;
        const int t    = lane & 3;
        const int rb   = (wid >> 1) * 16;
        const int cb   = (wid & 1)  * 32;

        float c[4][4];
        #pragma unroll
        for (int n = 0; n < 4; ++n)
            #pragma unroll
            for (int i = 0; i < 4; ++i) c[n][i] = 0.0f;

        gen(0, 0);
        __syncthreads();

        for (int b = 0; b < NB; ++b) {
            const int cur = b & 1;
            if (b + 1 < NB) gen(b + 1, cur ^ 1);   // overlap with MMA below

            const int rlo = sBminX[b] - basex, rhi = sBmaxX[b] - basex + W;
            const int clo = sBminY[b] - basey, chi = sBmaxY[b] - basey + W;
            if ((rb + 16 > rlo) && (rb < rhi) && (cb + 32 > clo) && (cb < chi)) {
                #pragma unroll
                for (int ks = 0; ks < 2; ++ks) {
                    const int k0 = ks * 8;
                    const unsigned a0 = ebx[cur][k0 + t][rb + g];
                    const unsigned a1 = ebx[cur][k0 + t][rb + g + 8];
                    const unsigned a2 = ebx[cur][k0 + t + 4][rb + g];
                    const unsigned a3 = ebx[cur][k0 + t + 4][rb + g + 8];
                    #pragma unroll
                    for (int n = 0; n < 4; ++n) {
                        const unsigned b0 = eby[cur][k0 + t][cb + n * 8 + g];
                        const unsigned b1 = eby[cur][k0 + t + 4][cb + n * 8 + g];
                        asm volatile(
                            "mma.sync.aligned.m16n8k8.row.col.f32.tf32.tf32.f32 "
                            "{%0,%1,%2,%3},{%4,%5,%6,%7},{%8,%9},{%0,%1,%2,%3};"
                            : "+f"(c[n][0]), "+f"(c[n][1]), "+f"(c[n][2]), "+f"(c[n][3])
                            : "r"(a0), "r"(a1), "r"(a2), "r"(a3), "r"(b0), "r"(b1));
                    }
                }
            }
            __syncthreads();
        }

        // ---- Epilogue: spread-address atomics
        const int row0 = basex + rb + g;
        const int row1 = row0 + 8;
        #pragma unroll
        for (int n = 0; n < 4; ++n) {
            const int col = basey + cb + n * 8 + 2 * t;
            if (c[n][0] != 0.0f && row0 < RES && col     < RES) atomicAdd(&out[row0 * RES + col],     c[n][0] * scale);
            if (c[n][1] != 0.0f && row0 < RES && col + 1 < RES) atomicAdd(&out[row0 * RES + col + 1], c[n][1] * scale);
            if (c[n][2] != 0.0f && row1 < RES && col     < RES) atomicAdd(&out[row1 * RES + col],     c[n][2] * scale);
            if (c[n][3] != 0.0f && row1 < RES && col + 1 < RES) atomicAdd(&out[row1 * RES + col + 1], c[n][3] * scale);
        }
    } else {
        // ---- Fallback (bbox exceeded tile; should never trigger for points in [0,1])
        for (int sl = 0; sl < CHUNK; ++sl) {
            const int   blkx = sBx[sl], blky = sBy[sl];
            const float cx = sCx[sl], cy = sCy[sl];
            for (int c2 = tid; c2 < W * W; c2 += NTHREADS) {
                const int wi = c2 >> 5, wj = c2 & 31;
                const int gx = blkx + wi, gy = blky + wj;
                const float dx = cx - (float)gx * DLT;
                const float dy = cy - (float)gy * DLT;
                const float w = __expf(-INV2SIG2 * (dx * dx + dy * dy));
                atomicAdd(&out[gx * RES + gy], w * scale);
            }
        }
    }
}

extern "C" void kernel_launch(void* const* d_in, const int* in_sizes, int n_in,
                              void* d_out, int out_size)
{
    (void)in_sizes; (void)n_in;
    const float* cp = (const float*)d_in[0];
    float* out = (float*)d_out;
    cudaMemsetAsync(out, 0, (size_t)out_size * sizeof(float), 0);
    bezier_raster_kernel<<<STEPS / CHUNK, NTHREADS>>>(cp, out);
}